// round 6
// baseline (speedup 1.0000x reference)
#include <cuda_runtime.h>
#include <math.h>
#include <stdint.h>

// ---------------------------------------------------------------------------
// RG-LRU forward, T=8192, D_MODEL=768, D_RNN=1024, KW=4.
// GEMMs: mma.sync.m16n8k8 TF32, 64x64 warp tiles (4 warps/CTA, 2 CTA/SM),
// ldmatrix fragments, cp.async 3-stage ring, 1 sync per chunk.
// ---------------------------------------------------------------------------

#define T_LEN 8192
#define DM    768
#define DR    1024
#define NCHK  64
#define CLEN  128

#define NSTAGE 3
#define BKF    32
#define STAGE_BYTES (2 * 128 * BKF * 4)

// scratch
__device__ float g_ab[T_LEN * DR];
__device__ float g_bb[T_LEN * DR];
__device__ float g_bcr[T_LEN * DR];
__device__ float g_at[T_LEN * DR];
__device__ float g_gx[T_LEN * DR];
__device__ float g_z[T_LEN * DR];
__device__ float g_wc[DR * DR * 4];
__device__ float g_xr[T_LEN * DM];
__device__ float g_w1r[2 * DR * DM];
__device__ float g_wrgp[2 * DR * DR];
__device__ float g_brgp[2 * DR];
__device__ float g_woutr[DM * DR];
__device__ float g_lam[DR];
__device__ float g_P[NCHK * DR];
__device__ float g_L[NCHK * DR];
__device__ float g_carry[NCHK * DR];
__device__ float g_zero[4096];

// ---------------- helpers ----------------
__device__ __forceinline__ uint32_t smem_u32(const void* p) {
    uint32_t a;
    asm("{ .reg .u64 t; cvta.to.shared.u64 t, %1; cvt.u32.u64 %0, t; }" : "=r"(a) : "l"(p));
    return a;
}
__device__ __forceinline__ uint32_t f2tf32(float f) {
    uint32_t u; asm("cvt.rna.tf32.f32 %0, %1;" : "=r"(u) : "f"(f)); return u;
}
__device__ __forceinline__ float roundtf(float f) { return __uint_as_float(f2tf32(f)); }

__device__ __forceinline__ float gelu_f(float x) {
    float x3 = x * x * x;
    float u  = 0.7978845608028654f * (x + 0.044715f * x3);
    return 0.5f * x * (1.0f + tanhf(u));
}
__device__ __forceinline__ float sigm(float x) { return 1.0f / (1.0f + expf(-x)); }

#define SW128(o) ((o) ^ ((((uint32_t)(o)) >> 3) & 0x70u))

__device__ __forceinline__ void cp16(uint32_t dst, const void* src, bool pred) {
    int sz = pred ? 16 : 0;
    asm volatile("cp.async.cg.shared.global [%0], [%1], 16, %2;\n"
                 :: "r"(dst), "l"(src), "r"(sz) : "memory");
}
__device__ __forceinline__ void cp_commit() {
    asm volatile("cp.async.commit_group;" ::: "memory");
}
__device__ __forceinline__ void ldsm4(uint32_t r[4], uint32_t addr) {
    asm volatile("ldmatrix.sync.aligned.m8n8.x4.shared.b16 {%0,%1,%2,%3}, [%4];"
                 : "=r"(r[0]), "=r"(r[1]), "=r"(r[2]), "=r"(r[3]) : "r"(addr));
}
__device__ __forceinline__ void mma_tf32(float d[4], const uint32_t a[4],
                                         const uint32_t b[2], const float c[4]) {
    asm volatile(
        "mma.sync.aligned.m16n8k8.row.col.f32.tf32.tf32.f32 "
        "{%0,%1,%2,%3}, {%4,%5,%6,%7}, {%8,%9}, {%10,%11,%12,%13};\n"
        : "=f"(d[0]), "=f"(d[1]), "=f"(d[2]), "=f"(d[3])
        : "r"(a[0]), "r"(a[1]), "r"(a[2]), "r"(a[3]),
          "r"(b[0]), "r"(b[1]),
          "f"(c[0]), "f"(c[1]), "f"(c[2]), "f"(c[3]));
}

// ---------------------------------------------------------------------------
// TF32 GEMM: C[M,N] = A[M,K] @ B[N,K]^T + bias, 128x128 CTA tile,
// 4 warps (2x2 grid of 64x64 warp tiles), 128 threads.
//   AMODE 0: plain A    AMODE 1: causal-conv gather (K = 4*1024 virtual)
//   EPI 0: raw   EPI 1: gelu / tf32-split   EPI 4: fused gates   EPI 5: rounded
// ---------------------------------------------------------------------------
template <int AMODE, int EPI>
__global__ __launch_bounds__(128, 2) void tgemm(
    const float* __restrict__ A, const float* __restrict__ B,
    const float* __restrict__ bias, float* __restrict__ C,
    float* __restrict__ C2, const float* __restrict__ Xbc,
    const float* __restrict__ lam, int M, int N, int K)
{
    extern __shared__ char dynsm[];
    const uint32_t sb = (smem_u32(dynsm) + 1023u) & ~1023u;

    const int tid  = threadIdx.x;
    const int wid  = tid >> 5;
    const int lane = tid & 31;
    const int bm   = blockIdx.y * 128;
    const int bn   = blockIdx.x * 128;
    const int wm   = (wid >> 1) * 64;     // 2x2 warp grid, 64x64 tiles
    const int wn   = (wid & 1) * 64;
    const int qr   = lane >> 2;
    const int qc   = lane & 3;

    const int arow  = wm + (lane & 15);
    const int ahalf = (lane >> 4) & 1;
    const int brow  = wn + (lane & 7) + ((lane >> 4) << 3);
    const int bhalf = (lane >> 3) & 1;

    float acc[4][8][4];
#pragma unroll
    for (int mi = 0; mi < 4; mi++)
#pragma unroll
        for (int ni = 0; ni < 8; ni++)
#pragma unroll
            for (int r = 0; r < 4; r++) acc[mi][ni][r] = 0.0f;

    const int nch = K / BKF;

    auto issue_chunk = [&](int c) {
        const int s = c % NSTAGE;
        const uint32_t abase = sb + s * STAGE_BYTES;
        const uint32_t bbase = abase + 128 * BKF * 4;
        const int k0 = c * BKF;
#pragma unroll
        for (int q = 0; q < 8; q++) {
            int id  = tid + q * 128;    // 0..1023
            int row = id >> 3;
            int c16 = id & 7;
            const float* asrc;
            bool pred = true;
            if (AMODE == 0) {
                asrc = A + (size_t)(bm + row) * K + k0 + c16 * 4;
            } else {
                int j    = k0 + c16 * 4;
                int tap  = j >> 10;
                int i    = j & 1023;
                int srct = bm + row + tap - 3;
                pred = (srct >= 0);
                asrc = A + (pred ? ((size_t)srct * 1024 + i) : 0);
            }
            cp16(abase + SW128(row * 128 + c16 * 16), asrc, pred);
            const float* bsrc = B + (size_t)(bn + row) * K + k0 + c16 * 4;
            cp16(bbase + SW128(row * 128 + c16 * 16), bsrc, true);
        }
        cp_commit();
    };

    auto compute = [&](int s) {
        const uint32_t abase = sb + s * STAGE_BYTES;
        const uint32_t bbase = abase + 128 * BKF * 4;
#pragma unroll
        for (int kb = 0; kb < 4; kb++) {
            uint32_t af[4][4];
#pragma unroll
            for (int mi = 0; mi < 4; mi++)
                ldsm4(af[mi], abase + SW128((arow + mi * 16) * 128 + kb * 32 + ahalf * 16));
            uint32_t bf[4][4];
#pragma unroll
            for (int p = 0; p < 4; p++)
                ldsm4(bf[p], bbase + SW128((brow + p * 16) * 128 + kb * 32 + bhalf * 16));
#pragma unroll
            for (int mi = 0; mi < 4; mi++)
#pragma unroll
                for (int ni = 0; ni < 8; ni++)
                    mma_tf32(acc[mi][ni], af[mi], &bf[ni >> 1][(ni & 1) * 2], acc[mi][ni]);
        }
    };

    // ---------------- mainloop: 1 sync per chunk ----------------
    issue_chunk(0);
    issue_chunk(1);
    for (int c = 0; c < nch; c++) {
        asm volatile("cp.async.wait_group %0;" :: "n"(1) : "memory");
        __syncthreads();
        compute(c % NSTAGE);
        if (c + 2 < nch) issue_chunk(c + 2);
        else             cp_commit();
    }

    // ---------------- epilogue ----------------
#pragma unroll
    for (int mi = 0; mi < 4; mi++) {
#pragma unroll
        for (int ni = 0; ni < 8; ni++) {
#pragma unroll
            for (int half = 0; half < 2; half++) {
                int m = bm + wm + mi * 16 + qr + half * 8;
                int n = bn + wn + ni * 8 + 2 * qc;
                float v0 = acc[mi][ni][half * 2 + 0] + bias[n];
                float v1 = acc[mi][ni][half * 2 + 1] + bias[n + 1];
                if (EPI == 0) {
                    C[(size_t)m * N + n]     = v0;
                    C[(size_t)m * N + n + 1] = v1;
                } else if (EPI == 1) {
                    if (n < DR) {
                        C[(size_t)m * DR + n]     = gelu_f(v0);
                        C[(size_t)m * DR + n + 1] = gelu_f(v1);
                    } else {
                        C2[(size_t)m * DR + (n - DR)]     = roundtf(v0);
                        C2[(size_t)m * DR + (n - DR) + 1] = roundtf(v1);
                    }
                } else if (EPI == 5) {
                    C[(size_t)m * N + n]     = roundtf(v0);
                    C[(size_t)m * N + n + 1] = roundtf(v1);
                } else {  // EPI == 4 : fused gate pair (inp, rec) for channel n>>1
                    int ch    = n >> 1;
                    float inp = sigm(v0);
                    float rec = sigm(v1);
                    float a   = expf(lam[ch] * rec);
                    float gx  = sqrtf(fmaxf(1.0f - a * a, 0.0f)) * inp *
                                Xbc[(size_t)m * DR + ch];
                    C[(size_t)m * DR + ch]  = a;
                    C2[(size_t)m * DR + ch] = gx;
                }
            }
        }
    }
}

// ---------------------------------------------------------------------------
// prep A (launch #1): w_rg permute + b_rg + lam + conv repack
__global__ void prep_a_kernel(const float* __restrict__ wrg,
                              const float* __restrict__ brg,
                              const float* __restrict__ Lambda,
                              const float* __restrict__ convw) {
    int gid = blockIdx.x * blockDim.x + threadIdx.x;   // grid covers DR*DR
    if (gid < 2 * DR) g_brgp[gid] = brg[(gid & 1) ? (DR + (gid >> 1)) : (gid >> 1)];
    if (gid < DR)     g_lam[gid]  = -8.0f * log1pf(expf(Lambda[gid]));
    // w_rg permute (float4 over k): items 0 .. 2*DR*DR/4-1
    if (gid < 2 * DR * DR / 4) {
        int r  = gid >> 8;
        int k4 = gid & 255;
        int srcr = (r & 1) ? (DR + (r >> 1)) : (r >> 1);
        float4 v = *reinterpret_cast<const float4*>(&wrg[(size_t)srcr * DR + k4 * 4]);
        v.x = roundtf(v.x); v.y = roundtf(v.y); v.z = roundtf(v.z); v.w = roundtf(v.w);
        *reinterpret_cast<float4*>(&g_wrgp[(size_t)r * DR + k4 * 4]) = v;
    }
    // conv repack: items 0 .. DR*DR-1
    if (gid < DR * DR) {
        int o = gid >> 10;
        int i = gid & 1023;
        float4 v = *reinterpret_cast<const float4*>(&convw[(size_t)gid * 4]);
        size_t base = (size_t)o * 4096 + i;
        g_wc[base]        = roundtf(v.x);
        g_wc[base + 1024] = roundtf(v.y);
        g_wc[base + 2048] = roundtf(v.z);
        g_wc[base + 3072] = roundtf(v.w);
    }
}

// prep B (launch #2): round x, w1, w_out (float4, range-partitioned)
__global__ void prep_b_kernel(const float* __restrict__ x,
                              const float* __restrict__ w1,
                              const float* __restrict__ wout) {
    int gid = blockIdx.x * blockDim.x + threadIdx.x;
    const int nx = T_LEN * DM / 4, n1 = 2 * DR * DM / 4, n2 = DM * DR / 4;
    const float4* s; float4* d; int i;
    if (gid < nx)           { s = (const float4*)x;    d = (float4*)g_xr;    i = gid; }
    else if (gid < nx + n1) { s = (const float4*)w1;   d = (float4*)g_w1r;   i = gid - nx; }
    else if (gid < nx + n1 + n2) { s = (const float4*)wout; d = (float4*)g_woutr; i = gid - nx - n1; }
    else return;
    float4 v = s[i];
    v.x = roundtf(v.x); v.y = roundtf(v.y); v.z = roundtf(v.z); v.w = roundtf(v.w);
    d[i] = v;
}

// ---- 3-phase chunked linear scan ----
__global__ void scan_phaseA_kernel() {
    int g = blockIdx.x * blockDim.x + threadIdx.x;
    if (g >= NCHK * DR) return;
    int c  = g & (DR - 1);
    int ch = g >> 10;
    size_t base = (size_t)ch * CLEN * DR + c;
    float P = 1.0f, L = 0.0f;
    for (int t = 0; t < CLEN; t++) {
        float a = g_at[base + (size_t)t * DR];
        float x = g_gx[base + (size_t)t * DR];
        L = fmaf(a, L, x);
        P *= a;
    }
    g_P[ch * DR + c] = P;
    g_L[ch * DR + c] = L;
}

__global__ void scan_phaseB_kernel() {
    int c = blockIdx.x * blockDim.x + threadIdx.x;
    if (c >= DR) return;
    float carry = 0.0f;
    for (int ch = 0; ch < NCHK; ch++) {
        g_carry[ch * DR + c] = carry;
        carry = fmaf(g_P[ch * DR + c], carry, g_L[ch * DR + c]);
    }
}

__global__ void scan_phaseC_kernel() {
    int g = blockIdx.x * blockDim.x + threadIdx.x;
    if (g >= NCHK * DR) return;
    int c  = g & (DR - 1);
    int ch = g >> 10;
    size_t base = (size_t)ch * CLEN * DR + c;
    float h = g_carry[ch * DR + c];
    for (int t = 0; t < CLEN; t++) {
        size_t o = base + (size_t)t * DR;
        h = fmaf(g_at[o], h, g_gx[o]);
        g_z[o] = roundtf(g_ab[o] * h);
    }
}

// ---------------------------------------------------------------------------
extern "C" void kernel_launch(void* const* d_in, const int* in_sizes, int n_in,
                              void* d_out, int out_size)
{
    const float* x      = (const float*)d_in[0];
    const float* w1     = (const float*)d_in[1];
    const float* b1     = (const float*)d_in[2];
    const float* conv_w = (const float*)d_in[3];
    const float* w_rg   = (const float*)d_in[4];
    const float* b_rg   = (const float*)d_in[5];
    const float* w_out  = (const float*)d_in[6];
    const float* b_out  = (const float*)d_in[7];
    const float* Lambda = (const float*)d_in[8];
    float* out = (float*)d_out;

    float *p_ab, *p_bb, *p_bcr, *p_at, *p_gx, *p_z, *p_wc, *p_zero;
    float *p_xr, *p_w1r, *p_wrgp, *p_brgp, *p_woutr, *p_lam;
    cudaGetSymbolAddress((void**)&p_ab,    g_ab);
    cudaGetSymbolAddress((void**)&p_bb,    g_bb);
    cudaGetSymbolAddress((void**)&p_bcr,   g_bcr);
    cudaGetSymbolAddress((void**)&p_at,    g_at);
    cudaGetSymbolAddress((void**)&p_gx,    g_gx);
    cudaGetSymbolAddress((void**)&p_z,     g_z);
    cudaGetSymbolAddress((void**)&p_wc,    g_wc);
    cudaGetSymbolAddress((void**)&p_zero,  g_zero);
    cudaGetSymbolAddress((void**)&p_xr,    g_xr);
    cudaGetSymbolAddress((void**)&p_w1r,   g_w1r);
    cudaGetSymbolAddress((void**)&p_wrgp,  g_wrgp);
    cudaGetSymbolAddress((void**)&p_brgp,  g_brgp);
    cudaGetSymbolAddress((void**)&p_woutr, g_woutr);
    cudaGetSymbolAddress((void**)&p_lam,   g_lam);

    const int smem_bytes = NSTAGE * STAGE_BYTES + 1024;
    cudaFuncSetAttribute(tgemm<0, 1>, cudaFuncAttributeMaxDynamicSharedMemorySize, smem_bytes);
    cudaFuncSetAttribute(tgemm<1, 5>, cudaFuncAttributeMaxDynamicSharedMemorySize, smem_bytes);
    cudaFuncSetAttribute(tgemm<0, 4>, cudaFuncAttributeMaxDynamicSharedMemorySize, smem_bytes);
    cudaFuncSetAttribute(tgemm<0, 0>, cudaFuncAttributeMaxDynamicSharedMemorySize, smem_bytes);

    // prep: exactly 2 launches so the conv GEMM is launch #4 (ncu target)
    prep_a_kernel<<<(DR * DR + 255) / 256, 256>>>(w_rg, b_rg, Lambda, conv_w);
    {
        int total = T_LEN * DM / 4 + 2 * DR * DM / 4 + DM * DR / 4;
        prep_b_kernel<<<(total + 255) / 256, 256>>>(x, w1, w_out);
    }

    // gemm1 (#3)
    {
        dim3 grid((2 * DR) / 128, T_LEN / 128);
        tgemm<0, 1><<<grid, 128, smem_bytes>>>(p_xr, p_w1r, b1, p_ab, p_bb,
                                               nullptr, nullptr, T_LEN, 2 * DR, DM);
    }
    // conv GEMM (#4 -> ncu capture target)
    {
        dim3 grid(DR / 128, T_LEN / 128);
        tgemm<1, 5><<<grid, 128, smem_bytes>>>(p_bb, p_wc, p_zero, p_bcr, nullptr,
                                               nullptr, nullptr, T_LEN, DR, DR * 4);
    }
    // gemm3 + fused gates
    {
        dim3 grid((2 * DR) / 128, T_LEN / 128);
        tgemm<0, 4><<<grid, 128, smem_bytes>>>(p_bcr, p_wrgp, p_brgp, p_at, p_gx,
                                               p_bcr, p_lam, T_LEN, 2 * DR, DR);
    }
    scan_phaseA_kernel<<<(NCHK * DR) / 256, 256>>>();
    scan_phaseB_kernel<<<(DR + 255) / 256, 256>>>();
    scan_phaseC_kernel<<<(NCHK * DR) / 256, 256>>>();
    // gemm4
    {
        dim3 grid(DM / 128, T_LEN / 128);
        tgemm<0, 0><<<grid, 128, smem_bytes>>>(p_z, p_woutr, b_out, out, nullptr,
                                               nullptr, nullptr, T_LEN, DM, DR);
    }
}

// round 8
// speedup vs baseline: 1.0332x; 1.0332x over previous
#include <cuda_runtime.h>
#include <math.h>
#include <stdint.h>

// ---------------------------------------------------------------------------
// RG-LRU forward, T=8192, D_MODEL=768, D_RNN=1024, KW=4.
// GEMMs: mma.sync.m16n8k8 TF32, 32x(BN/2) warp tiles (8 warps/CTA, 2 CTA/SM),
// ldmatrix fragments, cp.async 3-stage ring, early issue, 1 sync per chunk.
// gemm4 uses BN=64 tiles to cut wave-quantization tail.
// ---------------------------------------------------------------------------

#define T_LEN 8192
#define DM    768
#define DR    1024
#define NCHK  64
#define CLEN  128

#define NSTAGE 3
#define BKF    32

// scratch
__device__ float g_ab[T_LEN * DR];
__device__ float g_bb[T_LEN * DR];
__device__ float g_bcr[T_LEN * DR];
__device__ float g_at[T_LEN * DR];
__device__ float g_gx[T_LEN * DR];
__device__ float g_z[T_LEN * DR];
__device__ float g_wc[DR * DR * 4];
__device__ float g_xr[T_LEN * DM];
__device__ float g_w1r[2 * DR * DM];
__device__ float g_wrgp[2 * DR * DR];
__device__ float g_brgp[2 * DR];
__device__ float g_woutr[DM * DR];
__device__ float g_lam[DR];
__device__ float g_P[NCHK * DR];
__device__ float g_L[NCHK * DR];
__device__ float g_carry[NCHK * DR];
__device__ float g_zero[4096];

// ---------------- helpers ----------------
__device__ __forceinline__ uint32_t smem_u32(const void* p) {
    uint32_t a;
    asm("{ .reg .u64 t; cvta.to.shared.u64 t, %1; cvt.u32.u64 %0, t; }" : "=r"(a) : "l"(p));
    return a;
}
__device__ __forceinline__ uint32_t f2tf32(float f) {
    uint32_t u; asm("cvt.rna.tf32.f32 %0, %1;" : "=r"(u) : "f"(f)); return u;
}
__device__ __forceinline__ float roundtf(float f) { return __uint_as_float(f2tf32(f)); }

__device__ __forceinline__ float gelu_f(float x) {
    float x3 = x * x * x;
    float u  = 0.7978845608028654f * (x + 0.044715f * x3);
    return 0.5f * x * (1.0f + tanhf(u));
}
__device__ __forceinline__ float sigm(float x) { return 1.0f / (1.0f + expf(-x)); }

#define SW128(o) ((o) ^ ((((uint32_t)(o)) >> 3) & 0x70u))

__device__ __forceinline__ void cp16(uint32_t dst, const void* src, bool pred) {
    int sz = pred ? 16 : 0;
    asm volatile("cp.async.cg.shared.global [%0], [%1], 16, %2;\n"
                 :: "r"(dst), "l"(src), "r"(sz) : "memory");
}
__device__ __forceinline__ void cp_commit() {
    asm volatile("cp.async.commit_group;" ::: "memory");
}
__device__ __forceinline__ void ldsm4(uint32_t r[4], uint32_t addr) {
    asm volatile("ldmatrix.sync.aligned.m8n8.x4.shared.b16 {%0,%1,%2,%3}, [%4];"
                 : "=r"(r[0]), "=r"(r[1]), "=r"(r[2]), "=r"(r[3]) : "r"(addr));
}
__device__ __forceinline__ void mma_tf32(float d[4], const uint32_t a[4],
                                         const uint32_t b[2], const float c[4]) {
    asm volatile(
        "mma.sync.aligned.m16n8k8.row.col.f32.tf32.tf32.f32 "
        "{%0,%1,%2,%3}, {%4,%5,%6,%7}, {%8,%9}, {%10,%11,%12,%13};\n"
        : "=f"(d[0]), "=f"(d[1]), "=f"(d[2]), "=f"(d[3])
        : "r"(a[0]), "r"(a[1]), "r"(a[2]), "r"(a[3]),
          "r"(b[0]), "r"(b[1]),
          "f"(c[0]), "f"(c[1]), "f"(c[2]), "f"(c[3]));
}

// ---------------------------------------------------------------------------
// TF32 GEMM: C[M,N] = A[M,K] @ B[N,K]^T + bias, 128xBN CTA tile,
// 8 warps (4x2 grid of 32x(BN/2) warp tiles), 256 threads.
//   AMODE 0: plain A    AMODE 1: causal-conv gather (K = 4*1024 virtual)
//   EPI 0: raw   EPI 1: gelu / tf32-split   EPI 4: fused gates   EPI 5: rounded
// ---------------------------------------------------------------------------
template <int AMODE, int EPI, int BN>
__global__ __launch_bounds__(256, 2) void tgemm(
    const float* __restrict__ A, const float* __restrict__ B,
    const float* __restrict__ bias, float* __restrict__ C,
    float* __restrict__ C2, const float* __restrict__ Xbc,
    const float* __restrict__ lam, int M, int N, int K)
{
    constexpr int NI = BN / 16;            // 8-col mma tiles per warp
    constexpr int NP = BN / 32;            // B ldsm4 per kb per warp; ALSO B cp iters
    constexpr int ABYTES = 128 * BKF * 4;  // 16 KB
    constexpr int BBYTES = BN * BKF * 4;
    constexpr int SBYTES = ABYTES + BBYTES;

    extern __shared__ char dynsm[];
    const uint32_t sb = (smem_u32(dynsm) + 1023u) & ~1023u;

    const int tid  = threadIdx.x;
    const int wid  = tid >> 5;
    const int lane = tid & 31;
    const int bm   = blockIdx.y * 128;
    const int bn   = blockIdx.x * BN;
    const int wm   = (wid >> 1) * 32;
    const int wn   = (wid & 1) * (BN / 2);
    const int qr   = lane >> 2;
    const int qc   = lane & 3;

    const int arow  = wm + (lane & 15);
    const int ahalf = (lane >> 4) & 1;
    const int brow  = wn + (lane & 7) + ((lane >> 4) << 3);
    const int bhalf = (lane >> 3) & 1;

    float acc[2][NI][4];
#pragma unroll
    for (int mi = 0; mi < 2; mi++)
#pragma unroll
        for (int ni = 0; ni < NI; ni++)
#pragma unroll
            for (int r = 0; r < 4; r++) acc[mi][ni][r] = 0.0f;

    const int nch = K / BKF;

    auto issue_chunk = [&](int c) {
        const int s = c % NSTAGE;
        const uint32_t abase = sb + s * SBYTES;
        const uint32_t bbase = abase + ABYTES;
        const int k0 = c * BKF;
        // A: 128 rows x 8 c16 = 1024 cp16 over 256 threads -> 4 iterations
#pragma unroll
        for (int q = 0; q < 4; q++) {
            int id  = tid + q * 256;
            int row = id >> 3;
            int c16 = id & 7;
            const float* asrc;
            bool pred = true;
            if (AMODE == 0) {
                asrc = A + (size_t)(bm + row) * K + k0 + c16 * 4;
            } else {
                int j    = k0 + c16 * 4;
                int tap  = j >> 10;
                int i    = j & 1023;
                int srct = bm + row + tap - 3;
                pred = (srct >= 0);
                asrc = A + (pred ? ((size_t)srct * 1024 + i) : 0);
            }
            cp16(abase + SW128(row * 128 + c16 * 16), asrc, pred);
        }
        // B: BN rows x 8 c16 = BN*8 cp16 over 256 threads -> NP iterations
#pragma unroll
        for (int q = 0; q < NP; q++) {
            int id  = tid + q * 256;
            int row = id >> 3;               // 0 .. BN-1
            int c16 = id & 7;
            const float* bsrc = B + (size_t)(bn + row) * K + k0 + c16 * 4;
            cp16(bbase + SW128(row * 128 + c16 * 16), bsrc, true);
        }
        cp_commit();
    };

    auto compute = [&](int s) {
        const uint32_t abase = sb + s * SBYTES;
        const uint32_t bbase = abase + ABYTES;
#pragma unroll
        for (int kb = 0; kb < 4; kb++) {
            uint32_t af[2][4];
#pragma unroll
            for (int mi = 0; mi < 2; mi++)
                ldsm4(af[mi], abase + SW128((arow + mi * 16) * 128 + kb * 32 + ahalf * 16));
            uint32_t bf[NP][4];
#pragma unroll
            for (int p = 0; p < NP; p++)
                ldsm4(bf[p], bbase + SW128((brow + p * 16) * 128 + kb * 32 + bhalf * 16));
#pragma unroll
            for (int mi = 0; mi < 2; mi++)
#pragma unroll
                for (int ni = 0; ni < NI; ni++)
                    mma_tf32(acc[mi][ni], af[mi], &bf[ni >> 1][(ni & 1) * 2], acc[mi][ni]);
        }
    };

    // ---------------- mainloop: early issue, 1 sync per chunk ----------------
    issue_chunk(0);
    issue_chunk(1);
    for (int c = 0; c < nch; c++) {
        asm volatile("cp.async.wait_group %0;" :: "n"(1) : "memory");
        __syncthreads();
        if (c + 2 < nch) issue_chunk(c + 2);   // overlaps with compute below
        compute(c % NSTAGE);
    }

    // ---------------- epilogue ----------------
#pragma unroll
    for (int mi = 0; mi < 2; mi++) {
#pragma unroll
        for (int ni = 0; ni < NI; ni++) {
#pragma unroll
            for (int half = 0; half < 2; half++) {
                int m = bm + wm + mi * 16 + qr + half * 8;
                int n = bn + wn + ni * 8 + 2 * qc;
                float v0 = acc[mi][ni][half * 2 + 0] + bias[n];
                float v1 = acc[mi][ni][half * 2 + 1] + bias[n + 1];
                if (EPI == 0) {
                    C[(size_t)m * N + n]     = v0;
                    C[(size_t)m * N + n + 1] = v1;
                } else if (EPI == 1) {
                    if (n < DR) {
                        C[(size_t)m * DR + n]     = gelu_f(v0);
                        C[(size_t)m * DR + n + 1] = gelu_f(v1);
                    } else {
                        C2[(size_t)m * DR + (n - DR)]     = roundtf(v0);
                        C2[(size_t)m * DR + (n - DR) + 1] = roundtf(v1);
                    }
                } else if (EPI == 5) {
                    C[(size_t)m * N + n]     = roundtf(v0);
                    C[(size_t)m * N + n + 1] = roundtf(v1);
                } else {  // EPI == 4 : fused gate pair (inp, rec) for channel n>>1
                    int ch    = n >> 1;
                    float inp = sigm(v0);
                    float rec = sigm(v1);
                    float a   = expf(lam[ch] * rec);
                    float gx  = sqrtf(fmaxf(1.0f - a * a, 0.0f)) * inp *
                                Xbc[(size_t)m * DR + ch];
                    C[(size_t)m * DR + ch]  = a;
                    C2[(size_t)m * DR + ch] = gx;
                }
            }
        }
    }
}

// ---------------------------------------------------------------------------
// prep A: w_rg permute + b_rg + lam + conv repack
__global__ void prep_a_kernel(const float* __restrict__ wrg,
                              const float* __restrict__ brg,
                              const float* __restrict__ Lambda,
                              const float* __restrict__ convw) {
    int gid = blockIdx.x * blockDim.x + threadIdx.x;
    if (gid < 2 * DR) g_brgp[gid] = brg[(gid & 1) ? (DR + (gid >> 1)) : (gid >> 1)];
    if (gid < DR)     g_lam[gid]  = -8.0f * log1pf(expf(Lambda[gid]));
    if (gid < 2 * DR * DR / 4) {
        int r  = gid >> 8;
        int k4 = gid & 255;
        int srcr = (r & 1) ? (DR + (r >> 1)) : (r >> 1);
        float4 v = *reinterpret_cast<const float4*>(&wrg[(size_t)srcr * DR + k4 * 4]);
        v.x = roundtf(v.x); v.y = roundtf(v.y); v.z = roundtf(v.z); v.w = roundtf(v.w);
        *reinterpret_cast<float4*>(&g_wrgp[(size_t)r * DR + k4 * 4]) = v;
    }
    if (gid < DR * DR) {
        int o = gid >> 10;
        int i = gid & 1023;
        float4 v = *reinterpret_cast<const float4*>(&convw[(size_t)gid * 4]);
        size_t base = (size_t)o * 4096 + i;
        g_wc[base]        = roundtf(v.x);
        g_wc[base + 1024] = roundtf(v.y);
        g_wc[base + 2048] = roundtf(v.z);
        g_wc[base + 3072] = roundtf(v.w);
    }
}

// prep B: round x, w1, w_out
__global__ void prep_b_kernel(const float* __restrict__ x,
                              const float* __restrict__ w1,
                              const float* __restrict__ wout) {
    int gid = blockIdx.x * blockDim.x + threadIdx.x;
    const int nx = T_LEN * DM / 4, n1 = 2 * DR * DM / 4, n2 = DM * DR / 4;
    const float4* s; float4* d; int i;
    if (gid < nx)           { s = (const float4*)x;    d = (float4*)g_xr;    i = gid; }
    else if (gid < nx + n1) { s = (const float4*)w1;   d = (float4*)g_w1r;   i = gid - nx; }
    else if (gid < nx + n1 + n2) { s = (const float4*)wout; d = (float4*)g_woutr; i = gid - nx - n1; }
    else return;
    float4 v = s[i];
    v.x = roundtf(v.x); v.y = roundtf(v.y); v.z = roundtf(v.z); v.w = roundtf(v.w);
    d[i] = v;
}

// ---- 3-phase chunked linear scan ----
__global__ void scan_phaseA_kernel() {
    int g = blockIdx.x * blockDim.x + threadIdx.x;
    if (g >= NCHK * DR) return;
    int c  = g & (DR - 1);
    int ch = g >> 10;
    size_t base = (size_t)ch * CLEN * DR + c;
    float P = 1.0f, L = 0.0f;
    for (int t = 0; t < CLEN; t++) {
        float a = g_at[base + (size_t)t * DR];
        float x = g_gx[base + (size_t)t * DR];
        L = fmaf(a, L, x);
        P *= a;
    }
    g_P[ch * DR + c] = P;
    g_L[ch * DR + c] = L;
}

__global__ void scan_phaseB_kernel() {
    int c = blockIdx.x * blockDim.x + threadIdx.x;
    if (c >= DR) return;
    float carry = 0.0f;
    for (int ch = 0; ch < NCHK; ch++) {
        g_carry[ch * DR + c] = carry;
        carry = fmaf(g_P[ch * DR + c], carry, g_L[ch * DR + c]);
    }
}

__global__ void scan_phaseC_kernel() {
    int g = blockIdx.x * blockDim.x + threadIdx.x;
    if (g >= NCHK * DR) return;
    int c  = g & (DR - 1);
    int ch = g >> 10;
    size_t base = (size_t)ch * CLEN * DR + c;
    float h = g_carry[ch * DR + c];
    for (int t = 0; t < CLEN; t++) {
        size_t o = base + (size_t)t * DR;
        h = fmaf(g_at[o], h, g_gx[o]);
        g_z[o] = roundtf(g_ab[o] * h);
    }
}

// ---------------------------------------------------------------------------
extern "C" void kernel_launch(void* const* d_in, const int* in_sizes, int n_in,
                              void* d_out, int out_size)
{
    const float* x      = (const float*)d_in[0];
    const float* w1     = (const float*)d_in[1];
    const float* b1     = (const float*)d_in[2];
    const float* conv_w = (const float*)d_in[3];
    const float* w_rg   = (const float*)d_in[4];
    const float* b_rg   = (const float*)d_in[5];
    const float* w_out  = (const float*)d_in[6];
    const float* b_out  = (const float*)d_in[7];
    const float* Lambda = (const float*)d_in[8];
    float* out = (float*)d_out;

    float *p_ab, *p_bb, *p_bcr, *p_at, *p_gx, *p_z, *p_wc, *p_zero;
    float *p_xr, *p_w1r, *p_wrgp, *p_brgp, *p_woutr, *p_lam;
    cudaGetSymbolAddress((void**)&p_ab,    g_ab);
    cudaGetSymbolAddress((void**)&p_bb,    g_bb);
    cudaGetSymbolAddress((void**)&p_bcr,   g_bcr);
    cudaGetSymbolAddress((void**)&p_at,    g_at);
    cudaGetSymbolAddress((void**)&p_gx,    g_gx);
    cudaGetSymbolAddress((void**)&p_z,     g_z);
    cudaGetSymbolAddress((void**)&p_wc,    g_wc);
    cudaGetSymbolAddress((void**)&p_zero,  g_zero);
    cudaGetSymbolAddress((void**)&p_xr,    g_xr);
    cudaGetSymbolAddress((void**)&p_w1r,   g_w1r);
    cudaGetSymbolAddress((void**)&p_wrgp,  g_wrgp);
    cudaGetSymbolAddress((void**)&p_brgp,  g_brgp);
    cudaGetSymbolAddress((void**)&p_woutr, g_woutr);
    cudaGetSymbolAddress((void**)&p_lam,   g_lam);

    const int smem128 = NSTAGE * (128 + 128) * BKF * 4 + 1024;   // 97 KB
    const int smem64  = NSTAGE * (128 + 64)  * BKF * 4 + 1024;   // 73 KB
    cudaFuncSetAttribute(tgemm<0, 1, 128>, cudaFuncAttributeMaxDynamicSharedMemorySize, smem128);
    cudaFuncSetAttribute(tgemm<1, 5, 128>, cudaFuncAttributeMaxDynamicSharedMemorySize, smem128);
    cudaFuncSetAttribute(tgemm<0, 4, 128>, cudaFuncAttributeMaxDynamicSharedMemorySize, smem128);
    cudaFuncSetAttribute(tgemm<0, 0, 64>,  cudaFuncAttributeMaxDynamicSharedMemorySize, smem64);

    // prep: exactly 2 launches so the conv GEMM is launch #4 (ncu target)
    prep_a_kernel<<<(DR * DR + 255) / 256, 256>>>(w_rg, b_rg, Lambda, conv_w);
    {
        int total = T_LEN * DM / 4 + 2 * DR * DM / 4 + DM * DR / 4;
        prep_b_kernel<<<(total + 255) / 256, 256>>>(x, w1, w_out);
    }

    // gemm1 (#3)
    {
        dim3 grid((2 * DR) / 128, T_LEN / 128);
        tgemm<0, 1, 128><<<grid, 256, smem128>>>(p_xr, p_w1r, b1, p_ab, p_bb,
                                                 nullptr, nullptr, T_LEN, 2 * DR, DM);
    }
    // conv GEMM (#4 -> ncu capture target)
    {
        dim3 grid(DR / 128, T_LEN / 128);
        tgemm<1, 5, 128><<<grid, 256, smem128>>>(p_bb, p_wc, p_zero, p_bcr, nullptr,
                                                 nullptr, nullptr, T_LEN, DR, DR * 4);
    }
    // gemm3 + fused gates
    {
        dim3 grid((2 * DR) / 128, T_LEN / 128);
        tgemm<0, 4, 128><<<grid, 256, smem128>>>(p_bcr, p_wrgp, p_brgp, p_at, p_gx,
                                                 p_bcr, p_lam, T_LEN, 2 * DR, DR);
    }
    scan_phaseA_kernel<<<(NCHK * DR) / 256, 256>>>();
    scan_phaseB_kernel<<<(DR + 255) / 256, 256>>>();
    scan_phaseC_kernel<<<(NCHK * DR) / 256, 256>>>();
    // gemm4 (BN=64 to reduce wave tail: 768 CTAs)
    {
        dim3 grid(DM / 64, T_LEN / 128);
        tgemm<0, 0, 64><<<grid, 256, smem64>>>(p_z, p_woutr, b_out, out, nullptr,
                                               nullptr, nullptr, T_LEN, DM, DR);
    }
}

// round 9
// speedup vs baseline: 1.0571x; 1.0231x over previous
#include <cuda_runtime.h>
#include <math.h>
#include <stdint.h>

// ---------------------------------------------------------------------------
// RG-LRU forward, T=8192, D_MODEL=768, D_RNN=1024, KW=4.
// Per-GEMM tiling: conv (K=4096) uses 128-thr/64x64-warp-tile kernel (throughput);
// gemm1/3/4 (short K) use 256-thr/32x(BN/2) kernel (latency hiding).
// ---------------------------------------------------------------------------

#define T_LEN 8192
#define DM    768
#define DR    1024
#define NCHK  64
#define CLEN  128

#define NSTAGE 3
#define BKF    32

// scratch
__device__ float g_ab[T_LEN * DR];
__device__ float g_bb[T_LEN * DR];
__device__ float g_bcr[T_LEN * DR];
__device__ float g_at[T_LEN * DR];
__device__ float g_gx[T_LEN * DR];
__device__ float g_z[T_LEN * DR];
__device__ float g_wc[DR * DR * 4];
__device__ float g_xr[T_LEN * DM];
__device__ float g_w1r[2 * DR * DM];
__device__ float g_wrgp[2 * DR * DR];
__device__ float g_brgp[2 * DR];
__device__ float g_woutr[DM * DR];
__device__ float g_lam[DR];
__device__ float g_P[NCHK * DR];
__device__ float g_L[NCHK * DR];
__device__ float g_carry[NCHK * DR];
__device__ float g_zero[4096];

// ---------------- helpers ----------------
__device__ __forceinline__ uint32_t smem_u32(const void* p) {
    uint32_t a;
    asm("{ .reg .u64 t; cvta.to.shared.u64 t, %1; cvt.u32.u64 %0, t; }" : "=r"(a) : "l"(p));
    return a;
}
__device__ __forceinline__ uint32_t f2tf32(float f) {
    uint32_t u; asm("cvt.rna.tf32.f32 %0, %1;" : "=r"(u) : "f"(f)); return u;
}
__device__ __forceinline__ float roundtf(float f) { return __uint_as_float(f2tf32(f)); }

__device__ __forceinline__ float gelu_f(float x) {
    float x3 = x * x * x;
    float u  = 0.7978845608028654f * (x + 0.044715f * x3);
    return 0.5f * x * (1.0f + tanhf(u));
}
__device__ __forceinline__ float sigm(float x) { return 1.0f / (1.0f + expf(-x)); }

#define SW128(o) ((o) ^ ((((uint32_t)(o)) >> 3) & 0x70u))

__device__ __forceinline__ void cp16(uint32_t dst, const void* src, bool pred) {
    int sz = pred ? 16 : 0;
    asm volatile("cp.async.cg.shared.global [%0], [%1], 16, %2;\n"
                 :: "r"(dst), "l"(src), "r"(sz) : "memory");
}
__device__ __forceinline__ void cp_commit() {
    asm volatile("cp.async.commit_group;" ::: "memory");
}
__device__ __forceinline__ void ldsm4(uint32_t r[4], uint32_t addr) {
    asm volatile("ldmatrix.sync.aligned.m8n8.x4.shared.b16 {%0,%1,%2,%3}, [%4];"
                 : "=r"(r[0]), "=r"(r[1]), "=r"(r[2]), "=r"(r[3]) : "r"(addr));
}
__device__ __forceinline__ void mma_tf32(float d[4], const uint32_t a[4],
                                         const uint32_t b[2], const float c[4]) {
    asm volatile(
        "mma.sync.aligned.m16n8k8.row.col.f32.tf32.tf32.f32 "
        "{%0,%1,%2,%3}, {%4,%5,%6,%7}, {%8,%9}, {%10,%11,%12,%13};\n"
        : "=f"(d[0]), "=f"(d[1]), "=f"(d[2]), "=f"(d[3])
        : "r"(a[0]), "r"(a[1]), "r"(a[2]), "r"(a[3]),
          "r"(b[0]), "r"(b[1]),
          "f"(c[0]), "f"(c[1]), "f"(c[2]), "f"(c[3]));
}

// ---------------------------------------------------------------------------
// Variant A (short-K GEMMs): 256 threads, 4x2 warps, 32x(BN/2) warp tiles.
//   EPI 0: raw   EPI 1: gelu / tf32-split   EPI 4: fused gates
// ---------------------------------------------------------------------------
template <int EPI, int BN>
__global__ __launch_bounds__(256, 2) void tgemm(
    const float* __restrict__ A, const float* __restrict__ B,
    const float* __restrict__ bias, float* __restrict__ C,
    float* __restrict__ C2, const float* __restrict__ Xbc,
    const float* __restrict__ lam, int M, int N, int K)
{
    constexpr int NI = BN / 16;
    constexpr int NP = BN / 32;
    constexpr int ABYTES = 128 * BKF * 4;
    constexpr int BBYTES = BN * BKF * 4;
    constexpr int SBYTES = ABYTES + BBYTES;

    extern __shared__ char dynsm[];
    const uint32_t sb = (smem_u32(dynsm) + 1023u) & ~1023u;

    const int tid  = threadIdx.x;
    const int lane = tid & 31;
    const int wid  = tid >> 5;
    const int bm   = blockIdx.y * 128;
    const int bn   = blockIdx.x * BN;
    const int wm   = (wid >> 1) * 32;
    const int wn   = (wid & 1) * (BN / 2);
    const int qr   = lane >> 2;
    const int qc   = lane & 3;

    const int arow  = wm + (lane & 15);
    const int ahalf = (lane >> 4) & 1;
    const int brow  = wn + (lane & 7) + ((lane >> 4) << 3);
    const int bhalf = (lane >> 3) & 1;

    float acc[2][NI][4];
#pragma unroll
    for (int mi = 0; mi < 2; mi++)
#pragma unroll
        for (int ni = 0; ni < NI; ni++)
#pragma unroll
            for (int r = 0; r < 4; r++) acc[mi][ni][r] = 0.0f;

    const int nch = K / BKF;

    auto issue_chunk = [&](int c) {
        const int s = c % NSTAGE;
        const uint32_t abase = sb + s * SBYTES;
        const uint32_t bbase = abase + ABYTES;
        const int k0 = c * BKF;
#pragma unroll
        for (int q = 0; q < 4; q++) {
            int id  = tid + q * 256;
            int row = id >> 3;
            int c16 = id & 7;
            const float* asrc = A + (size_t)(bm + row) * K + k0 + c16 * 4;
            cp16(abase + SW128(row * 128 + c16 * 16), asrc, true);
        }
#pragma unroll
        for (int q = 0; q < NP; q++) {
            int id  = tid + q * 256;
            int row = id >> 3;
            int c16 = id & 7;
            const float* bsrc = B + (size_t)(bn + row) * K + k0 + c16 * 4;
            cp16(bbase + SW128(row * 128 + c16 * 16), bsrc, true);
        }
        cp_commit();
    };

    auto compute = [&](int s) {
        const uint32_t abase = sb + s * SBYTES;
        const uint32_t bbase = abase + ABYTES;
#pragma unroll
        for (int kb = 0; kb < 4; kb++) {
            uint32_t af[2][4];
#pragma unroll
            for (int mi = 0; mi < 2; mi++)
                ldsm4(af[mi], abase + SW128((arow + mi * 16) * 128 + kb * 32 + ahalf * 16));
            uint32_t bf[NP][4];
#pragma unroll
            for (int p = 0; p < NP; p++)
                ldsm4(bf[p], bbase + SW128((brow + p * 16) * 128 + kb * 32 + bhalf * 16));
#pragma unroll
            for (int mi = 0; mi < 2; mi++)
#pragma unroll
                for (int ni = 0; ni < NI; ni++)
                    mma_tf32(acc[mi][ni], af[mi], &bf[ni >> 1][(ni & 1) * 2], acc[mi][ni]);
        }
    };

    issue_chunk(0);
    issue_chunk(1);
    for (int c = 0; c < nch; c++) {
        asm volatile("cp.async.wait_group %0;" :: "n"(1) : "memory");
        __syncthreads();
        if (c + 2 < nch) issue_chunk(c + 2);
        compute(c % NSTAGE);
    }

#pragma unroll
    for (int mi = 0; mi < 2; mi++) {
#pragma unroll
        for (int ni = 0; ni < NI; ni++) {
#pragma unroll
            for (int half = 0; half < 2; half++) {
                int m = bm + wm + mi * 16 + qr + half * 8;
                int n = bn + wn + ni * 8 + 2 * qc;
                float v0 = acc[mi][ni][half * 2 + 0] + bias[n];
                float v1 = acc[mi][ni][half * 2 + 1] + bias[n + 1];
                if (EPI == 0) {
                    C[(size_t)m * N + n]     = v0;
                    C[(size_t)m * N + n + 1] = v1;
                } else if (EPI == 1) {
                    if (n < DR) {
                        C[(size_t)m * DR + n]     = gelu_f(v0);
                        C[(size_t)m * DR + n + 1] = gelu_f(v1);
                    } else {
                        C2[(size_t)m * DR + (n - DR)]     = roundtf(v0);
                        C2[(size_t)m * DR + (n - DR) + 1] = roundtf(v1);
                    }
                } else {  // EPI == 4
                    int ch    = n >> 1;
                    float inp = sigm(v0);
                    float rec = sigm(v1);
                    float a   = expf(lam[ch] * rec);
                    float gx  = sqrtf(fmaxf(1.0f - a * a, 0.0f)) * inp *
                                Xbc[(size_t)m * DR + ch];
                    C[(size_t)m * DR + ch]  = a;
                    C2[(size_t)m * DR + ch] = gx;
                }
            }
        }
    }
}

// ---------------------------------------------------------------------------
// Variant B (conv GEMM, K=4096): 128 threads, 2x2 warps, 64x64 warp tiles.
// A is the causal-conv gather; epilogue writes tf32-rounded output.
// (Exact R6 kernel, verified 360.8us @ tensor 62.7%.)
// ---------------------------------------------------------------------------
__global__ __launch_bounds__(128, 2) void tgemm_conv(
    const float* __restrict__ A, const float* __restrict__ B,
    float* __restrict__ C, int M, int N, int K)
{
    constexpr int SBYTES = 2 * 128 * BKF * 4;
    extern __shared__ char dynsm[];
    const uint32_t sb = (smem_u32(dynsm) + 1023u) & ~1023u;

    const int tid  = threadIdx.x;
    const int wid  = tid >> 5;
    const int lane = tid & 31;
    const int bm   = blockIdx.y * 128;
    const int bn   = blockIdx.x * 128;
    const int wm   = (wid >> 1) * 64;
    const int wn   = (wid & 1) * 64;
    const int qr   = lane >> 2;
    const int qc   = lane & 3;

    const int arow  = wm + (lane & 15);
    const int ahalf = (lane >> 4) & 1;
    const int brow  = wn + (lane & 7) + ((lane >> 4) << 3);
    const int bhalf = (lane >> 3) & 1;

    float acc[4][8][4];
#pragma unroll
    for (int mi = 0; mi < 4; mi++)
#pragma unroll
        for (int ni = 0; ni < 8; ni++)
#pragma unroll
            for (int r = 0; r < 4; r++) acc[mi][ni][r] = 0.0f;

    const int nch = K / BKF;

    auto issue_chunk = [&](int c) {
        const int s = c % NSTAGE;
        const uint32_t abase = sb + s * SBYTES;
        const uint32_t bbase = abase + 128 * BKF * 4;
        const int k0 = c * BKF;
#pragma unroll
        for (int q = 0; q < 8; q++) {
            int id  = tid + q * 128;
            int row = id >> 3;
            int c16 = id & 7;
            // A: conv gather
            int j    = k0 + c16 * 4;
            int tap  = j >> 10;
            int i    = j & 1023;
            int srct = bm + row + tap - 3;
            bool pred = (srct >= 0);
            const float* asrc = A + (pred ? ((size_t)srct * 1024 + i) : 0);
            cp16(abase + SW128(row * 128 + c16 * 16), asrc, pred);
            const float* bsrc = B + (size_t)(bn + row) * K + k0 + c16 * 4;
            cp16(bbase + SW128(row * 128 + c16 * 16), bsrc, true);
        }
        cp_commit();
    };

    auto compute = [&](int s) {
        const uint32_t abase = sb + s * SBYTES;
        const uint32_t bbase = abase + 128 * BKF * 4;
#pragma unroll
        for (int kb = 0; kb < 4; kb++) {
            uint32_t af[4][4];
#pragma unroll
            for (int mi = 0; mi < 4; mi++)
                ldsm4(af[mi], abase + SW128((arow + mi * 16) * 128 + kb * 32 + ahalf * 16));
            uint32_t bf[4][4];
#pragma unroll
            for (int p = 0; p < 4; p++)
                ldsm4(bf[p], bbase + SW128((brow + p * 16) * 128 + kb * 32 + bhalf * 16));
#pragma unroll
            for (int mi = 0; mi < 4; mi++)
#pragma unroll
                for (int ni = 0; ni < 8; ni++)
                    mma_tf32(acc[mi][ni], af[mi], &bf[ni >> 1][(ni & 1) * 2], acc[mi][ni]);
        }
    };

    issue_chunk(0);
    issue_chunk(1);
    for (int c = 0; c < nch; c++) {
        asm volatile("cp.async.wait_group %0;" :: "n"(1) : "memory");
        __syncthreads();
        compute(c % NSTAGE);
        if (c + 2 < nch) issue_chunk(c + 2);
    }

#pragma unroll
    for (int mi = 0; mi < 4; mi++) {
#pragma unroll
        for (int ni = 0; ni < 8; ni++) {
#pragma unroll
            for (int half = 0; half < 2; half++) {
                int m = bm + wm + mi * 16 + qr + half * 8;
                int n = bn + wn + ni * 8 + 2 * qc;
                C[(size_t)m * N + n]     = roundtf(acc[mi][ni][half * 2 + 0]);
                C[(size_t)m * N + n + 1] = roundtf(acc[mi][ni][half * 2 + 1]);
            }
        }
    }
}

// ---------------------------------------------------------------------------
// prep A: w_rg permute + b_rg + lam + conv repack
__global__ void prep_a_kernel(const float* __restrict__ wrg,
                              const float* __restrict__ brg,
                              const float* __restrict__ Lambda,
                              const float* __restrict__ convw) {
    int gid = blockIdx.x * blockDim.x + threadIdx.x;
    if (gid < 2 * DR) g_brgp[gid] = brg[(gid & 1) ? (DR + (gid >> 1)) : (gid >> 1)];
    if (gid < DR)     g_lam[gid]  = -8.0f * log1pf(expf(Lambda[gid]));
    if (gid < 2 * DR * DR / 4) {
        int r  = gid >> 8;
        int k4 = gid & 255;
        int srcr = (r & 1) ? (DR + (r >> 1)) : (r >> 1);
        float4 v = *reinterpret_cast<const float4*>(&wrg[(size_t)srcr * DR + k4 * 4]);
        v.x = roundtf(v.x); v.y = roundtf(v.y); v.z = roundtf(v.z); v.w = roundtf(v.w);
        *reinterpret_cast<float4*>(&g_wrgp[(size_t)r * DR + k4 * 4]) = v;
    }
    if (gid < DR * DR) {
        int o = gid >> 10;
        int i = gid & 1023;
        float4 v = *reinterpret_cast<const float4*>(&convw[(size_t)gid * 4]);
        size_t base = (size_t)o * 4096 + i;
        g_wc[base]        = roundtf(v.x);
        g_wc[base + 1024] = roundtf(v.y);
        g_wc[base + 2048] = roundtf(v.z);
        g_wc[base + 3072] = roundtf(v.w);
    }
}

// prep B: round x, w1, w_out
__global__ void prep_b_kernel(const float* __restrict__ x,
                              const float* __restrict__ w1,
                              const float* __restrict__ wout) {
    int gid = blockIdx.x * blockDim.x + threadIdx.x;
    const int nx = T_LEN * DM / 4, n1 = 2 * DR * DM / 4, n2 = DM * DR / 4;
    const float4* s; float4* d; int i;
    if (gid < nx)           { s = (const float4*)x;    d = (float4*)g_xr;    i = gid; }
    else if (gid < nx + n1) { s = (const float4*)w1;   d = (float4*)g_w1r;   i = gid - nx; }
    else if (gid < nx + n1 + n2) { s = (const float4*)wout; d = (float4*)g_woutr; i = gid - nx - n1; }
    else return;
    float4 v = s[i];
    v.x = roundtf(v.x); v.y = roundtf(v.y); v.z = roundtf(v.z); v.w = roundtf(v.w);
    d[i] = v;
}

// ---- 3-phase chunked linear scan ----
__global__ void scan_phaseA_kernel() {
    int g = blockIdx.x * blockDim.x + threadIdx.x;
    if (g >= NCHK * DR) return;
    int c  = g & (DR - 1);
    int ch = g >> 10;
    size_t base = (size_t)ch * CLEN * DR + c;
    float P = 1.0f, L = 0.0f;
    for (int t = 0; t < CLEN; t++) {
        float a = g_at[base + (size_t)t * DR];
        float x = g_gx[base + (size_t)t * DR];
        L = fmaf(a, L, x);
        P *= a;
    }
    g_P[ch * DR + c] = P;
    g_L[ch * DR + c] = L;
}

__global__ void scan_phaseB_kernel() {
    int c = blockIdx.x * blockDim.x + threadIdx.x;
    if (c >= DR) return;
    float carry = 0.0f;
    for (int ch = 0; ch < NCHK; ch++) {
        g_carry[ch * DR + c] = carry;
        carry = fmaf(g_P[ch * DR + c], carry, g_L[ch * DR + c]);
    }
}

__global__ void scan_phaseC_kernel() {
    int g = blockIdx.x * blockDim.x + threadIdx.x;
    if (g >= NCHK * DR) return;
    int c  = g & (DR - 1);
    int ch = g >> 10;
    size_t base = (size_t)ch * CLEN * DR + c;
    float h = g_carry[ch * DR + c];
    for (int t = 0; t < CLEN; t++) {
        size_t o = base + (size_t)t * DR;
        h = fmaf(g_at[o], h, g_gx[o]);
        g_z[o] = roundtf(g_ab[o] * h);
    }
}

// ---------------------------------------------------------------------------
extern "C" void kernel_launch(void* const* d_in, const int* in_sizes, int n_in,
                              void* d_out, int out_size)
{
    const float* x      = (const float*)d_in[0];
    const float* w1     = (const float*)d_in[1];
    const float* b1     = (const float*)d_in[2];
    const float* conv_w = (const float*)d_in[3];
    const float* w_rg   = (const float*)d_in[4];
    const float* b_rg   = (const float*)d_in[5];
    const float* w_out  = (const float*)d_in[6];
    const float* b_out  = (const float*)d_in[7];
    const float* Lambda = (const float*)d_in[8];
    float* out = (float*)d_out;

    float *p_ab, *p_bb, *p_bcr, *p_at, *p_gx, *p_z, *p_wc, *p_zero;
    float *p_xr, *p_w1r, *p_wrgp, *p_brgp, *p_woutr, *p_lam;
    cudaGetSymbolAddress((void**)&p_ab,    g_ab);
    cudaGetSymbolAddress((void**)&p_bb,    g_bb);
    cudaGetSymbolAddress((void**)&p_bcr,   g_bcr);
    cudaGetSymbolAddress((void**)&p_at,    g_at);
    cudaGetSymbolAddress((void**)&p_gx,    g_gx);
    cudaGetSymbolAddress((void**)&p_z,     g_z);
    cudaGetSymbolAddress((void**)&p_wc,    g_wc);
    cudaGetSymbolAddress((void**)&p_zero,  g_zero);
    cudaGetSymbolAddress((void**)&p_xr,    g_xr);
    cudaGetSymbolAddress((void**)&p_w1r,   g_w1r);
    cudaGetSymbolAddress((void**)&p_wrgp,  g_wrgp);
    cudaGetSymbolAddress((void**)&p_brgp,  g_brgp);
    cudaGetSymbolAddress((void**)&p_woutr, g_woutr);
    cudaGetSymbolAddress((void**)&p_lam,   g_lam);

    const int smem128 = NSTAGE * (128 + 128) * BKF * 4 + 1024;   // 97 KB
    const int smem64  = NSTAGE * (128 + 64)  * BKF * 4 + 1024;   // 73 KB
    cudaFuncSetAttribute(tgemm<1, 128>, cudaFuncAttributeMaxDynamicSharedMemorySize, smem128);
    cudaFuncSetAttribute(tgemm_conv,    cudaFuncAttributeMaxDynamicSharedMemorySize, smem128);
    cudaFuncSetAttribute(tgemm<4, 128>, cudaFuncAttributeMaxDynamicSharedMemorySize, smem128);
    cudaFuncSetAttribute(tgemm<0, 64>,  cudaFuncAttributeMaxDynamicSharedMemorySize, smem64);

    // prep: exactly 2 launches so the conv GEMM is launch #4 (ncu target)
    prep_a_kernel<<<(DR * DR + 255) / 256, 256>>>(w_rg, b_rg, Lambda, conv_w);
    {
        int total = T_LEN * DM / 4 + 2 * DR * DM / 4 + DM * DR / 4;
        prep_b_kernel<<<(total + 255) / 256, 256>>>(x, w1, w_out);
    }

    // gemm1 (#3): h = x @ w1^T + b1 ; gelu -> g_ab, rounded raw -> g_bb
    {
        dim3 grid((2 * DR) / 128, T_LEN / 128);
        tgemm<1, 128><<<grid, 256, smem128>>>(p_xr, p_w1r, b1, p_ab, p_bb,
                                              nullptr, nullptr, T_LEN, 2 * DR, DM);
    }
    // conv GEMM (#4 -> ncu capture target): 64x64 warp-tile variant
    {
        dim3 grid(DR / 128, T_LEN / 128);
        tgemm_conv<<<grid, 128, smem128>>>(p_bb, p_wc, p_bcr, T_LEN, DR, DR * 4);
    }
    // gemm3 + fused gates
    {
        dim3 grid((2 * DR) / 128, T_LEN / 128);
        tgemm<4, 128><<<grid, 256, smem128>>>(p_bcr, p_wrgp, p_brgp, p_at, p_gx,
                                              p_bcr, p_lam, T_LEN, 2 * DR, DR);
    }
    scan_phaseA_kernel<<<(NCHK * DR) / 256, 256>>>();
    scan_phaseB_kernel<<<(DR + 255) / 256, 256>>>();
    scan_phaseC_kernel<<<(NCHK * DR) / 256, 256>>>();
    // gemm4 (BN=64)
    {
        dim3 grid(DM / 64, T_LEN / 128);
        tgemm<0, 64><<<grid, 256, smem64>>>(p_z, p_woutr, b_out, out, nullptr,
                                            nullptr, nullptr, T_LEN, DM, DR);
    }
}

// round 10
// speedup vs baseline: 1.1295x; 1.0684x over previous
#include <cuda_runtime.h>
#include <math.h>
#include <stdint.h>

// ---------------------------------------------------------------------------
// RG-LRU forward, T=8192, D_MODEL=768, D_RNN=1024, KW=4.
// Critical-path restructure: gemm1 split into bb-half (critical) + ab-half
// (slack); ab-half fused into the conv kernel as heterogeneous tiles to fill
// conv's wave-quantization tail. bb padded with 3 zero rows -> branchless
// conv gather.
// ---------------------------------------------------------------------------

#define T_LEN 8192
#define DM    768
#define DR    1024
#define NCHK  64
#define CLEN  128

#define NSTAGE 3
#define BKF    32

// scratch
__device__ float g_ab[T_LEN * DR];
__device__ float g_bbp[(T_LEN + 3) * DR];   // 3 zero rows + bb (rows 3..8194)
__device__ float g_bcr[T_LEN * DR];
__device__ float g_at[T_LEN * DR];
__device__ float g_gx[T_LEN * DR];
__device__ float g_z[T_LEN * DR];
__device__ float g_wc[DR * DR * 4];
__device__ float g_xr[T_LEN * DM];
__device__ float g_w1r[2 * DR * DM];
__device__ float g_wrgp[2 * DR * DR];
__device__ float g_brgp[2 * DR];
__device__ float g_woutr[DM * DR];
__device__ float g_lam[DR];
__device__ float g_P[NCHK * DR];
__device__ float g_L[NCHK * DR];
__device__ float g_carry[NCHK * DR];

// ---------------- helpers ----------------
__device__ __forceinline__ uint32_t smem_u32(const void* p) {
    uint32_t a;
    asm("{ .reg .u64 t; cvta.to.shared.u64 t, %1; cvt.u32.u64 %0, t; }" : "=r"(a) : "l"(p));
    return a;
}
__device__ __forceinline__ uint32_t f2tf32(float f) {
    uint32_t u; asm("cvt.rna.tf32.f32 %0, %1;" : "=r"(u) : "f"(f)); return u;
}
__device__ __forceinline__ float roundtf(float f) { return __uint_as_float(f2tf32(f)); }

__device__ __forceinline__ float gelu_f(float x) {
    float x3 = x * x * x;
    float u  = 0.7978845608028654f * (x + 0.044715f * x3);
    return 0.5f * x * (1.0f + tanhf(u));
}
__device__ __forceinline__ float sigm(float x) { return 1.0f / (1.0f + expf(-x)); }

#define SW128(o) ((o) ^ ((((uint32_t)(o)) >> 3) & 0x70u))

__device__ __forceinline__ void cp16(uint32_t dst, const void* src) {
    asm volatile("cp.async.cg.shared.global [%0], [%1], 16;\n"
                 :: "r"(dst), "l"(src) : "memory");
}
__device__ __forceinline__ void cp_commit() {
    asm volatile("cp.async.commit_group;" ::: "memory");
}
__device__ __forceinline__ void ldsm4(uint32_t r[4], uint32_t addr) {
    asm volatile("ldmatrix.sync.aligned.m8n8.x4.shared.b16 {%0,%1,%2,%3}, [%4];"
                 : "=r"(r[0]), "=r"(r[1]), "=r"(r[2]), "=r"(r[3]) : "r"(addr));
}
__device__ __forceinline__ void mma_tf32(float d[4], const uint32_t a[4],
                                         const uint32_t b[2], const float c[4]) {
    asm volatile(
        "mma.sync.aligned.m16n8k8.row.col.f32.tf32.tf32.f32 "
        "{%0,%1,%2,%3}, {%4,%5,%6,%7}, {%8,%9}, {%10,%11,%12,%13};\n"
        : "=f"(d[0]), "=f"(d[1]), "=f"(d[2]), "=f"(d[3])
        : "r"(a[0]), "r"(a[1]), "r"(a[2]), "r"(a[3]),
          "r"(b[0]), "r"(b[1]),
          "f"(c[0]), "f"(c[1]), "f"(c[2]), "f"(c[3]));
}

// ---------------------------------------------------------------------------
// Variant A (short-K GEMMs): 256 threads, 4x2 warps, 32x(BN/2) warp tiles.
//   EPI 0: raw+bias   EPI 4: fused gates   EPI 5: tf32-rounded (no bias)
// ---------------------------------------------------------------------------
template <int EPI, int BN>
__global__ __launch_bounds__(256, 2) void tgemm(
    const float* __restrict__ A, const float* __restrict__ B,
    const float* __restrict__ bias, float* __restrict__ C,
    float* __restrict__ C2, const float* __restrict__ Xbc,
    const float* __restrict__ lam, int M, int N, int K)
{
    constexpr int NI = BN / 16;
    constexpr int NP = BN / 32;
    constexpr int ABYTES = 128 * BKF * 4;
    constexpr int BBYTES = BN * BKF * 4;
    constexpr int SBYTES = ABYTES + BBYTES;

    extern __shared__ char dynsm[];
    const uint32_t sb = (smem_u32(dynsm) + 1023u) & ~1023u;

    const int tid  = threadIdx.x;
    const int lane = tid & 31;
    const int wid  = tid >> 5;
    const int bm   = blockIdx.y * 128;
    const int bn   = blockIdx.x * BN;
    const int wm   = (wid >> 1) * 32;
    const int wn   = (wid & 1) * (BN / 2);
    const int qr   = lane >> 2;
    const int qc   = lane & 3;

    const int arow  = wm + (lane & 15);
    const int ahalf = (lane >> 4) & 1;
    const int brow  = wn + (lane & 7) + ((lane >> 4) << 3);
    const int bhalf = (lane >> 3) & 1;

    float acc[2][NI][4];
#pragma unroll
    for (int mi = 0; mi < 2; mi++)
#pragma unroll
        for (int ni = 0; ni < NI; ni++)
#pragma unroll
            for (int r = 0; r < 4; r++) acc[mi][ni][r] = 0.0f;

    const int nch = K / BKF;

    auto issue_chunk = [&](int c) {
        const int s = c % NSTAGE;
        const uint32_t abase = sb + s * SBYTES;
        const uint32_t bbase = abase + ABYTES;
        const int k0 = c * BKF;
#pragma unroll
        for (int q = 0; q < 4; q++) {
            int id  = tid + q * 256;
            int row = id >> 3;
            int c16 = id & 7;
            cp16(abase + SW128(row * 128 + c16 * 16),
                 A + (size_t)(bm + row) * K + k0 + c16 * 4);
        }
#pragma unroll
        for (int q = 0; q < NP; q++) {
            int id  = tid + q * 256;
            int row = id >> 3;
            int c16 = id & 7;
            cp16(bbase + SW128(row * 128 + c16 * 16),
                 B + (size_t)(bn + row) * K + k0 + c16 * 4);
        }
        cp_commit();
    };

    auto compute = [&](int s) {
        const uint32_t abase = sb + s * SBYTES;
        const uint32_t bbase = abase + ABYTES;
#pragma unroll
        for (int kb = 0; kb < 4; kb++) {
            uint32_t af[2][4];
#pragma unroll
            for (int mi = 0; mi < 2; mi++)
                ldsm4(af[mi], abase + SW128((arow + mi * 16) * 128 + kb * 32 + ahalf * 16));
            uint32_t bf[NP][4];
#pragma unroll
            for (int p = 0; p < NP; p++)
                ldsm4(bf[p], bbase + SW128((brow + p * 16) * 128 + kb * 32 + bhalf * 16));
#pragma unroll
            for (int mi = 0; mi < 2; mi++)
#pragma unroll
                for (int ni = 0; ni < NI; ni++)
                    mma_tf32(acc[mi][ni], af[mi], &bf[ni >> 1][(ni & 1) * 2], acc[mi][ni]);
        }
    };

    issue_chunk(0);
    issue_chunk(1);
    for (int c = 0; c < nch; c++) {
        asm volatile("cp.async.wait_group %0;" :: "n"(1) : "memory");
        __syncthreads();
        if (c + 2 < nch) issue_chunk(c + 2);
        compute(c % NSTAGE);
    }

#pragma unroll
    for (int mi = 0; mi < 2; mi++) {
#pragma unroll
        for (int ni = 0; ni < NI; ni++) {
#pragma unroll
            for (int half = 0; half < 2; half++) {
                int m = bm + wm + mi * 16 + qr + half * 8;
                int n = bn + wn + ni * 8 + 2 * qc;
                if (EPI == 0) {
                    C[(size_t)m * N + n]     = acc[mi][ni][half * 2 + 0] + bias[n];
                    C[(size_t)m * N + n + 1] = acc[mi][ni][half * 2 + 1] + bias[n + 1];
                } else if (EPI == 5) {
                    C[(size_t)m * N + n]     = roundtf(acc[mi][ni][half * 2 + 0] + bias[n]);
                    C[(size_t)m * N + n + 1] = roundtf(acc[mi][ni][half * 2 + 1] + bias[n + 1]);
                } else {  // EPI == 4 : fused gate pair (inp, rec) for channel n>>1
                    float v0  = acc[mi][ni][half * 2 + 0] + bias[n];
                    float v1  = acc[mi][ni][half * 2 + 1] + bias[n + 1];
                    int ch    = n >> 1;
                    float inp = sigm(v0);
                    float rec = sigm(v1);
                    float a   = expf(lam[ch] * rec);
                    float gx  = sqrtf(fmaxf(1.0f - a * a, 0.0f)) * inp *
                                Xbc[(size_t)m * DR + ch];
                    C[(size_t)m * DR + ch]  = a;
                    C2[(size_t)m * DR + ch] = gx;
                }
            }
        }
    }
}

// ---------------------------------------------------------------------------
// Merged heterogeneous kernel: 128 threads, 2x2 warps, 64x64 warp tiles.
//   blockIdx.x < conv_tiles : conv tile  (A = padded-bb gather, K=4096,
//                             epilogue tf32-round -> g_bcr)
//   else                    : gemm1-ab tile (A = xr, K=768,
//                             epilogue bias+gelu -> g_ab)
// Conv tiles dispatch first; short ab tiles pack into conv's tail wave.
// ---------------------------------------------------------------------------
__global__ __launch_bounds__(128, 2) void tgemm_merged(
    const float* __restrict__ Abb, const float* __restrict__ Bwc,
    float* __restrict__ Cbc,
    const float* __restrict__ Axr, const float* __restrict__ Bw1,
    const float* __restrict__ bias1, float* __restrict__ Cab,
    int conv_tiles)
{
    constexpr int SBYTES = 2 * 128 * BKF * 4;
    extern __shared__ char dynsm[];
    const uint32_t sb = (smem_u32(dynsm) + 1023u) & ~1023u;

    const bool isconv = ((int)blockIdx.x) < conv_tiles;
    const int  tile   = isconv ? blockIdx.x : (blockIdx.x - conv_tiles);
    const int  bn     = (tile & 7) * 128;      // N = 1024 for both duties
    const int  bm     = (tile >> 3) * 128;
    const int  K      = isconv ? (DR * 4) : DM;
    const float* B    = isconv ? Bwc : Bw1;

    const int tid  = threadIdx.x;
    const int wid  = tid >> 5;
    const int lane = tid & 31;
    const int wm   = (wid >> 1) * 64;
    const int wn   = (wid & 1) * 64;
    const int qr   = lane >> 2;
    const int qc   = lane & 3;

    const int arow  = wm + (lane & 15);
    const int ahalf = (lane >> 4) & 1;
    const int brow  = wn + (lane & 7) + ((lane >> 4) << 3);
    const int bhalf = (lane >> 3) & 1;

    float acc[4][8][4];
#pragma unroll
    for (int mi = 0; mi < 4; mi++)
#pragma unroll
        for (int ni = 0; ni < 8; ni++)
#pragma unroll
            for (int r = 0; r < 4; r++) acc[mi][ni][r] = 0.0f;

    const int nch = K / BKF;

    auto issue_chunk = [&](int c) {
        const int s = c % NSTAGE;
        const uint32_t abase = sb + s * SBYTES;
        const uint32_t bbase = abase + 128 * BKF * 4;
        const int k0 = c * BKF;
#pragma unroll
        for (int q = 0; q < 8; q++) {
            int id  = tid + q * 128;
            int row = id >> 3;
            int c16 = id & 7;
            const float* asrc;
            if (isconv) {
                int j   = k0 + c16 * 4;
                int tap = j >> 10;
                int i   = j & 1023;
                // padded bb: logical row (bm+row+tap-3) lives at (bm+row+tap)
                asrc = Abb + (size_t)(bm + row + tap) * 1024 + i;
            } else {
                asrc = Axr + (size_t)(bm + row) * DM + k0 + c16 * 4;
            }
            cp16(abase + SW128(row * 128 + c16 * 16), asrc);
            cp16(bbase + SW128(row * 128 + c16 * 16),
                 B + (size_t)(bn + row) * K + k0 + c16 * 4);
        }
        cp_commit();
    };

    auto compute = [&](int s) {
        const uint32_t abase = sb + s * SBYTES;
        const uint32_t bbase = abase + 128 * BKF * 4;
#pragma unroll
        for (int kb = 0; kb < 4; kb++) {
            uint32_t af[4][4];
#pragma unroll
            for (int mi = 0; mi < 4; mi++)
                ldsm4(af[mi], abase + SW128((arow + mi * 16) * 128 + kb * 32 + ahalf * 16));
            uint32_t bf[4][4];
#pragma unroll
            for (int p = 0; p < 4; p++)
                ldsm4(bf[p], bbase + SW128((brow + p * 16) * 128 + kb * 32 + bhalf * 16));
#pragma unroll
            for (int mi = 0; mi < 4; mi++)
#pragma unroll
                for (int ni = 0; ni < 8; ni++)
                    mma_tf32(acc[mi][ni], af[mi], &bf[ni >> 1][(ni & 1) * 2], acc[mi][ni]);
        }
    };

    issue_chunk(0);
    issue_chunk(1);
    for (int c = 0; c < nch; c++) {
        asm volatile("cp.async.wait_group %0;" :: "n"(1) : "memory");
        __syncthreads();
        compute(c % NSTAGE);
        if (c + 2 < nch) issue_chunk(c + 2);
    }

#pragma unroll
    for (int mi = 0; mi < 4; mi++) {
#pragma unroll
        for (int ni = 0; ni < 8; ni++) {
#pragma unroll
            for (int half = 0; half < 2; half++) {
                int m = bm + wm + mi * 16 + qr + half * 8;
                int n = bn + wn + ni * 8 + 2 * qc;
                float v0 = acc[mi][ni][half * 2 + 0];
                float v1 = acc[mi][ni][half * 2 + 1];
                if (isconv) {
                    Cbc[(size_t)m * DR + n]     = roundtf(v0);
                    Cbc[(size_t)m * DR + n + 1] = roundtf(v1);
                } else {
                    Cab[(size_t)m * DR + n]     = gelu_f(v0 + bias1[n]);
                    Cab[(size_t)m * DR + n + 1] = gelu_f(v1 + bias1[n + 1]);
                }
            }
        }
    }
}

// ---------------------------------------------------------------------------
// prep (single kernel): w_rg permute + b_rg + lam + conv repack + round x/w1/wout
__global__ void prep_kernel(const float* __restrict__ wrg,
                            const float* __restrict__ brg,
                            const float* __restrict__ Lambda,
                            const float* __restrict__ convw,
                            const float* __restrict__ x,
                            const float* __restrict__ w1,
                            const float* __restrict__ wout) {
    int gid = blockIdx.x * blockDim.x + threadIdx.x;
    if (gid < 2 * DR) g_brgp[gid] = brg[(gid & 1) ? (DR + (gid >> 1)) : (gid >> 1)];
    if (gid < DR)     g_lam[gid]  = -8.0f * log1pf(expf(Lambda[gid]));
    if (gid < 2 * DR * DR / 4) {      // w_rg permute, float4 over k
        int r  = gid >> 8;
        int k4 = gid & 255;
        int srcr = (r & 1) ? (DR + (r >> 1)) : (r >> 1);
        float4 v = *reinterpret_cast<const float4*>(&wrg[(size_t)srcr * DR + k4 * 4]);
        v.x = roundtf(v.x); v.y = roundtf(v.y); v.z = roundtf(v.z); v.w = roundtf(v.w);
        *reinterpret_cast<float4*>(&g_wrgp[(size_t)r * DR + k4 * 4]) = v;
    }
    if (gid < DR * DR) {              // conv repack [o][i][k] -> [o][k*1024+i]
        int o = gid >> 10;
        int i = gid & 1023;
        float4 v = *reinterpret_cast<const float4*>(&convw[(size_t)gid * 4]);
        size_t base = (size_t)o * 4096 + i;
        g_wc[base]        = roundtf(v.x);
        g_wc[base + 1024] = roundtf(v.y);
        g_wc[base + 2048] = roundtf(v.z);
        g_wc[base + 3072] = roundtf(v.w);
    }
    {                                  // round x / w1 / wout, float4
        const int nx = T_LEN * DM / 4, n1 = 2 * DR * DM / 4, n2 = DM * DR / 4;
        const float4* s = nullptr; float4* d = nullptr; int i = 0;
        if (gid < nx)                { s = (const float4*)x;    d = (float4*)g_xr;    i = gid; }
        else if (gid < nx + n1)      { s = (const float4*)w1;   d = (float4*)g_w1r;   i = gid - nx; }
        else if (gid < nx + n1 + n2) { s = (const float4*)wout; d = (float4*)g_woutr; i = gid - nx - n1; }
        if (s) {
            float4 v = s[i];
            v.x = roundtf(v.x); v.y = roundtf(v.y); v.z = roundtf(v.z); v.w = roundtf(v.w);
            d[i] = v;
        }
    }
}

// ---- 3-phase chunked linear scan ----
__global__ void scan_phaseA_kernel() {
    int g = blockIdx.x * blockDim.x + threadIdx.x;
    if (g >= NCHK * DR) return;
    int c  = g & (DR - 1);
    int ch = g >> 10;
    size_t base = (size_t)ch * CLEN * DR + c;
    float P = 1.0f, L = 0.0f;
    for (int t = 0; t < CLEN; t++) {
        float a = g_at[base + (size_t)t * DR];
        float x = g_gx[base + (size_t)t * DR];
        L = fmaf(a, L, x);
        P *= a;
    }
    g_P[ch * DR + c] = P;
    g_L[ch * DR + c] = L;
}

__global__ void scan_phaseB_kernel() {
    int c = blockIdx.x * blockDim.x + threadIdx.x;
    if (c >= DR) return;
    float carry = 0.0f;
    for (int ch = 0; ch < NCHK; ch++) {
        g_carry[ch * DR + c] = carry;
        carry = fmaf(g_P[ch * DR + c], carry, g_L[ch * DR + c]);
    }
}

__global__ void scan_phaseC_kernel() {
    int g = blockIdx.x * blockDim.x + threadIdx.x;
    if (g >= NCHK * DR) return;
    int c  = g & (DR - 1);
    int ch = g >> 10;
    size_t base = (size_t)ch * CLEN * DR + c;
    float h = g_carry[ch * DR + c];
    for (int t = 0; t < CLEN; t++) {
        size_t o = base + (size_t)t * DR;
        h = fmaf(g_at[o], h, g_gx[o]);
        g_z[o] = roundtf(g_ab[o] * h);
    }
}

// ---------------------------------------------------------------------------
extern "C" void kernel_launch(void* const* d_in, const int* in_sizes, int n_in,
                              void* d_out, int out_size)
{
    const float* x      = (const float*)d_in[0];
    const float* w1     = (const float*)d_in[1];
    const float* b1     = (const float*)d_in[2];
    const float* conv_w = (const float*)d_in[3];
    const float* w_rg   = (const float*)d_in[4];
    const float* b_rg   = (const float*)d_in[5];
    const float* w_out  = (const float*)d_in[6];
    const float* b_out  = (const float*)d_in[7];
    const float* Lambda = (const float*)d_in[8];
    float* out = (float*)d_out;

    float *p_ab, *p_bbp, *p_bcr, *p_at, *p_gx, *p_z, *p_wc;
    float *p_xr, *p_w1r, *p_wrgp, *p_brgp, *p_woutr, *p_lam;
    cudaGetSymbolAddress((void**)&p_ab,    g_ab);
    cudaGetSymbolAddress((void**)&p_bbp,   g_bbp);
    cudaGetSymbolAddress((void**)&p_bcr,   g_bcr);
    cudaGetSymbolAddress((void**)&p_at,    g_at);
    cudaGetSymbolAddress((void**)&p_gx,    g_gx);
    cudaGetSymbolAddress((void**)&p_z,     g_z);
    cudaGetSymbolAddress((void**)&p_wc,    g_wc);
    cudaGetSymbolAddress((void**)&p_xr,    g_xr);
    cudaGetSymbolAddress((void**)&p_w1r,   g_w1r);
    cudaGetSymbolAddress((void**)&p_wrgp,  g_wrgp);
    cudaGetSymbolAddress((void**)&p_brgp,  g_brgp);
    cudaGetSymbolAddress((void**)&p_woutr, g_woutr);
    cudaGetSymbolAddress((void**)&p_lam,   g_lam);

    const int smem128 = NSTAGE * (128 + 128) * BKF * 4 + 1024;   // 97 KB
    const int smem64  = NSTAGE * (128 + 64)  * BKF * 4 + 1024;   // 73 KB
    cudaFuncSetAttribute(tgemm<5, 128>, cudaFuncAttributeMaxDynamicSharedMemorySize, smem128);
    cudaFuncSetAttribute(tgemm_merged,  cudaFuncAttributeMaxDynamicSharedMemorySize, smem128);
    cudaFuncSetAttribute(tgemm<4, 128>, cudaFuncAttributeMaxDynamicSharedMemorySize, smem128);
    cudaFuncSetAttribute(tgemm<0, 64>,  cudaFuncAttributeMaxDynamicSharedMemorySize, smem64);

    // #1 prep (single launch)
    {
        int total = T_LEN * DM / 4 + 2 * DR * DM / 4 + DM * DR / 4;  // largest range
        int grid  = total > DR * DR ? total : DR * DR;
        prep_kernel<<<(grid + 255) / 256, 256>>>(w_rg, b_rg, Lambda, conv_w, x, w1, w_out);
    }

    // #2 gemm1 bb-half: bb = x @ w1[1024:]^T + b1[1024:], rounded -> g_bbp+3 rows
    {
        dim3 grid(DR / 128, T_LEN / 128);
        tgemm<5, 128><<<grid, 256, smem128>>>(p_xr, p_w1r + (size_t)DR * DM,
                                              b1 + DR, p_bbp + 3 * DR, nullptr,
                                              nullptr, nullptr, T_LEN, DR, DM);
    }
    // #3 merged: conv tiles (512, first) + gemm1 ab-half tiles (512)
    {
        tgemm_merged<<<1024, 128, smem128>>>(p_bbp, p_wc, p_bcr,
                                             p_xr, p_w1r, b1, p_ab, 512);
    }
    // #4 gemm3 + fused gates (ncu capture target)
    {
        dim3 grid((2 * DR) / 128, T_LEN / 128);
        tgemm<4, 128><<<grid, 256, smem128>>>(p_bcr, p_wrgp, p_brgp, p_at, p_gx,
                                              p_bcr, p_lam, T_LEN, 2 * DR, DR);
    }
    scan_phaseA_kernel<<<(NCHK * DR) / 256, 256>>>();
    scan_phaseB_kernel<<<(DR + 255) / 256, 256>>>();
    scan_phaseC_kernel<<<(NCHK * DR) / 256, 256>>>();
    // #8 gemm4
    {
        dim3 grid(DM / 64, T_LEN / 128);
        tgemm<0, 64><<<grid, 256, smem64>>>(p_z, p_woutr, b_out, out, nullptr,
                                            nullptr, nullptr, T_LEN, DM, DR);
    }
}